// round 16
// baseline (speedup 1.0000x reference)
#include <cuda_runtime.h>
#include <cuda_fp16.h>
#include <cstdint>

#define NN 50000
#define EE 250000
#define HH 4
#define CC 64
#define DNODE 256
#define EDD 194
#define KPAD 256
#define NOUT 256
#define KEDGE 224

// ---------------- scratch (device globals; no runtime allocation) ----------------
__device__ float  g_q   [(size_t)NN * DNODE];
__device__ float  g_k   [(size_t)NN * DNODE];
__device__ float  g_v   [(size_t)NN * DNODE];
__device__ float  g_skip[(size_t)NN * DNODE];
__device__ __half g_eh  [(size_t)EE * DNODE];   // edge embeddings, fp16, original order

// edge sort-by-dst (once per call)
__device__ int g_cnt [NN];
__device__ int g_off [NN + 1];
__device__ int g_pos [NN];
__device__ int g_order[EE];
__device__ int g_srcs [EE];

// fp16 operands: single-limb A, hi/lo weights
__device__ __half g_xa [(size_t)NN * KPAD];     // node features (x, then relu(h1))
__device__ __half g_ea [(size_t)EE * KPAD];     // edge features
__device__ __half g_wh [10][(size_t)NOUT * KPAD];  // per layer: Wq,Wk,Wv,Ws,We
__device__ __half g_wl [10][(size_t)NOUT * KPAD];
__device__ float  g_bias[2][4 * NOUT];

// ==================== fp16 2-product HMMA GEMM (single-barrier pipeline) ====================
// C = A * (Whi + Wlo)^T ; A single fp16 limb, W fp16 hi/lo, fp32 accum.
#define BM 128
#define BN 128
#define BK 32
#define NTHR 512
#define NSTAGE 3
#define LDS_A 40
#define TSZ (BM * LDS_A)            // halves per tile
#define STAGE_ELEMS (3 * TSZ)       // A | Whi | Wlo
#define GEMM_SMEM (NSTAGE * STAGE_ELEMS * 2)

__device__ __forceinline__ uint32_t smem_u32(const void* p) {
    uint32_t a;
    asm("{ .reg .u64 t; cvta.to.shared.u64 t, %1; cvt.u32.u64 %0, t; }" : "=r"(a) : "l"(p));
    return a;
}
__device__ __forceinline__ void cpa16(uint32_t dst, const void* src, int szbytes) {
    asm volatile("cp.async.ca.shared.global [%0], [%1], 16, %2;"
                 :: "r"(dst), "l"(src), "r"(szbytes));
}
#define CP_COMMIT() asm volatile("cp.async.commit_group;" ::: "memory")
#define CP_WAIT(n)  asm volatile("cp.async.wait_group %0;" :: "n"(n) : "memory")

__device__ __forceinline__ void ldsm4(uint32_t* r, uint32_t a) {
    asm volatile("ldmatrix.sync.aligned.m8n8.x4.shared.b16 {%0,%1,%2,%3}, [%4];"
                 : "=r"(r[0]), "=r"(r[1]), "=r"(r[2]), "=r"(r[3]) : "r"(a));
}
__device__ __forceinline__ void mma_fp16(float* c, const uint32_t* a, const uint32_t* b) {
    asm volatile(
        "mma.sync.aligned.m16n8k16.row.col.f32.f16.f16.f32 "
        "{%0,%1,%2,%3}, {%4,%5,%6,%7}, {%8,%9}, {%0,%1,%2,%3};"
        : "+f"(c[0]), "+f"(c[1]), "+f"(c[2]), "+f"(c[3])
        : "r"(a[0]), "r"(a[1]), "r"(a[2]), "r"(a[3]), "r"(b[0]), "r"(b[1]));
}

// If EH != nullptr: fp16 epilogue into EH (edge GEMM). Else fp32 into C0..C3 + bias.
__global__ __launch_bounds__(NTHR) void gemm_f16(
    const __half* __restrict__ A,
    const __half* __restrict__ Whi, const __half* __restrict__ Wlo,
    const float* __restrict__ bias,
    float* __restrict__ C0, float* __restrict__ C1,
    float* __restrict__ C2, float* __restrict__ C3,
    __half* __restrict__ EH,
    int M, int K)
{
    extern __shared__ __half smem[];

    const int tid  = threadIdx.x;
    const int wid  = tid >> 5;
    const int lane = tid & 31;
    const int m0   = blockIdx.x * BM;
    const int nglob0 = blockIdx.y * BN;

    const int wm = (wid & 3) * 32;
    const int wn = (wid >> 2) * 32;
    const int gr  = lane >> 2;
    const int tig = lane & 3;

    const int r0  = tid >> 2;
    const int cg0 = (tid & 3) * 8;
    const int gmA = m0 + r0;
    const int aok = (gmA < M) ? 16 : 0;
    const size_t arow = (size_t)(aok ? gmA : 0) * KPAD;
    const size_t brow = (size_t)(nglob0 + r0) * KPAD;

    const int nk = K / BK;

    float acc[2][4][4];
#pragma unroll
    for (int i = 0; i < 2; i++)
#pragma unroll
        for (int j = 0; j < 4; j++)
#pragma unroll
            for (int r = 0; r < 4; r++) acc[i][j][r] = 0.f;

    uint32_t sbase = smem_u32(smem);

    auto load_stage = [&](int st, int kc) {
        uint32_t b = sbase + (uint32_t)(st * STAGE_ELEMS) * 2;
        uint32_t d = b + (uint32_t)(r0 * LDS_A + cg0) * 2;
        cpa16(d,                    A   + arow + kc + cg0, aok);
        cpa16(d + (uint32_t)TSZ*2,  Whi + brow + kc + cg0, 16);
        cpa16(d + (uint32_t)TSZ*4,  Wlo + brow + kc + cg0, 16);
        CP_COMMIT();
    };

    const int aRow = lane & 15;
    const int aCol = (lane >> 4) * 8;
    const uint32_t aOff = (uint32_t)((wm + aRow) * LDS_A + aCol) * 2;
    const int bRow = wn + (lane & 7) + ((lane >> 4) << 3);
    const int bCol = ((lane >> 3) & 1) * 8;
    const uint32_t bOff = (uint32_t)(bRow * LDS_A + bCol) * 2;

    load_stage(0, 0);
    if (nk > 1) load_stage(1, BK);

    for (int ki = 0; ki < nk; ki++) {
        if (ki + 1 < nk) {
            CP_WAIT(1);
        } else {
            CP_WAIT(0);
        }
        __syncthreads();

        uint32_t stb = sbase + (uint32_t)((ki % NSTAGE) * STAGE_ELEMS) * 2;
        uint32_t aB  = stb;
        uint32_t bHiB = stb + TSZ * 2, bLoB = stb + TSZ * 4;

#pragma unroll
        for (int ks = 0; ks < BK; ks += 16) {
            uint32_t ah[2][4];
#pragma unroll
            for (int mt = 0; mt < 2; mt++) {
                uint32_t o = aOff + (uint32_t)(mt * 16 * LDS_A + ks) * 2;
                ldsm4(ah[mt], aB + o);
            }
            uint32_t bhf[8], blf[8];
#pragma unroll
            for (int p = 0; p < 2; p++) {
                uint32_t o = bOff + (uint32_t)(p * 16 * LDS_A + ks) * 2;
                ldsm4(bhf + 4 * p, bHiB + o);
                ldsm4(blf + 4 * p, bLoB + o);
            }
#pragma unroll
            for (int mt = 0; mt < 2; mt++)
#pragma unroll
                for (int nt = 0; nt < 4; nt++) {
                    mma_fp16(acc[mt][nt], ah[mt], bhf + nt * 2);
                    mma_fp16(acc[mt][nt], ah[mt], blf + nt * 2);
                }
        }

        if (ki + 2 < nk) load_stage((ki + 2) % NSTAGE, (ki + 2) * BK);
    }

    // ---- epilogue ----
    if (EH == nullptr) {
        const int ob = blockIdx.y >> 1;
        float* C = (ob == 0) ? C0 : (ob == 1) ? C1 : (ob == 2) ? C2 : C3;
        const int n0l = (blockIdx.y & 1) * BN;
#pragma unroll
        for (int nt = 0; nt < 4; nt++) {
            int lc = wn + nt * 8 + tig * 2;
            float2 b2 = *(const float2*)(bias + nglob0 + lc);
            int gc = n0l + lc;
#pragma unroll
            for (int mt = 0; mt < 2; mt++) {
                int gm = m0 + wm + mt * 16 + gr;
                if (gm < M) {
                    float2 v0 = make_float2(acc[mt][nt][0] + b2.x, acc[mt][nt][1] + b2.y);
                    *(float2*)(C + (size_t)gm * NOUT + gc) = v0;
                }
                if (gm + 8 < M) {
                    float2 v1 = make_float2(acc[mt][nt][2] + b2.x, acc[mt][nt][3] + b2.y);
                    *(float2*)(C + (size_t)(gm + 8) * NOUT + gc) = v1;
                }
            }
        }
    } else {
#pragma unroll
        for (int nt = 0; nt < 4; nt++) {
            int gc = nglob0 + wn + nt * 8 + tig * 2;
#pragma unroll
            for (int mt = 0; mt < 2; mt++) {
                int gm = m0 + wm + mt * 16 + gr;
                if (gm < M) {
                    __half2 h0 = __floats2half2_rn(acc[mt][nt][0], acc[mt][nt][1]);
                    *(__half2*)(EH + (size_t)gm * NOUT + gc) = h0;
                }
                if (gm + 8 < M) {
                    __half2 h1 = __floats2half2_rn(acc[mt][nt][2], acc[mt][nt][3]);
                    *(__half2*)(EH + (size_t)(gm + 8) * NOUT + gc) = h1;
                }
            }
        }
    }
}

// ==================== conversion kernels ====================
// features -> single fp16 limb, zero-padded to KPAD (only k < kmax written)
__global__ void feat_f16(const float* __restrict__ X, __half* __restrict__ A,
                         int M, int Kin, int kmax)
{
    int idx = blockIdx.x * blockDim.x + threadIdx.x;
    if (idx >= M * KPAD) return;
    int k = idx & (KPAD - 1);
    if (k >= kmax) return;
    float v = (k < Kin) ? X[(size_t)(idx >> 8) * Kin + k] : 0.f;
    A[idx] = __float2half(v);
}

// weight [Kin, 256] -> transposed fp16 hi/lo [256 n][KPAD k]
__global__ void split_weight_f16(const float* __restrict__ W,
                                 __half* __restrict__ hi, __half* __restrict__ lo,
                                 int Kin)
{
    int idx = blockIdx.x * blockDim.x + threadIdx.x;
    if (idx >= NOUT * KPAD) return;
    int n = idx & 255, k = idx >> 8;
    float v = (k < Kin) ? W[(size_t)k * NOUT + n] : 0.f;
    __half h = __float2half(v);
    hi[(size_t)n * KPAD + k] = h;
    lo[(size_t)n * KPAD + k] = __float2half(v - __half2float(h));
}

__global__ void pack_bias(const float* __restrict__ bq, const float* __restrict__ bk,
                          const float* __restrict__ bv, const float* __restrict__ bs,
                          float* __restrict__ out)
{
    int i = blockIdx.x * blockDim.x + threadIdx.x;
    if (i >= 4 * NOUT) return;
    const float* src = (i < 256) ? bq : (i < 512) ? bk : (i < 768) ? bv : bs;
    out[i] = src[i & 255];
}

// ==================== edge sort-by-dst (once per call) ====================
__global__ void zero_cnt(int* __restrict__ cnt) {
    int i = blockIdx.x * blockDim.x + threadIdx.x;
    if (i < NN) cnt[i] = 0;
}
__global__ void hist_dst(const int* __restrict__ dst, int* __restrict__ cnt) {
    int i = blockIdx.x * blockDim.x + threadIdx.x;
    if (i < EE) atomicAdd(&cnt[dst[i]], 1);
}
__global__ __launch_bounds__(1024) void scan_cnt(const int* __restrict__ cnt,
                                                 int* __restrict__ off, int* __restrict__ pos)
{
    __shared__ int ssum[1024];
    const int tid = threadIdx.x;
    const int PER = (NN + 1023) / 1024;
    const int base = tid * PER;
    int s = 0;
    for (int j = 0; j < PER; j++) {
        int i = base + j;
        if (i < NN) s += cnt[i];
    }
    ssum[tid] = s;
    __syncthreads();
    for (int d = 1; d < 1024; d <<= 1) {
        int t = (tid >= d) ? ssum[tid - d] : 0;
        __syncthreads();
        ssum[tid] += t;
        __syncthreads();
    }
    int run = (tid > 0) ? ssum[tid - 1] : 0;
    for (int j = 0; j < PER; j++) {
        int i = base + j;
        if (i < NN) {
            off[i] = run;
            pos[i] = run;
            run += cnt[i];
        }
    }
    if (tid == 1023) off[NN] = run;
}
__global__ void scatter_edges(const int* __restrict__ dst, const int* __restrict__ src,
                              int* __restrict__ pos, int* __restrict__ order,
                              int* __restrict__ srcs)
{
    int i = blockIdx.x * blockDim.x + threadIdx.x;
    if (i >= EE) return;
    int p = atomicAdd(&pos[dst[i]], 1);
    order[p] = i;
    srcs[p] = src[i];
}

// ==================== fused per-dst attention (softmax + agg + skip + out) ====================
// mode 1: relu + fp16 write into node-A buffer (layer-2 GEMM input); mode 0: f32 out
__global__ __launch_bounds__(256) void edge_dst(
    const float* __restrict__ q, const float* __restrict__ k,
    const __half* __restrict__ eemb, const float* __restrict__ v,
    const int* __restrict__ srcs, const int* __restrict__ order,
    const int* __restrict__ off, const float* __restrict__ skip,
    float* __restrict__ outf, __half* __restrict__ aout,
    int mode)
{
    int w = (blockIdx.x * blockDim.x + threadIdx.x) >> 5;
    if (w >= NN) return;
    const int lane = threadIdx.x & 31;
    const int h = lane >> 3;
    const int part = lane & 7;
    const int co = h * CC + part * 8;

    const int start = off[w], end = off[w + 1];

    const float4* qp = (const float4*)(q + (size_t)w * DNODE + co);
    float4 q0 = qp[0], q1 = qp[1];

    float acc[8] = {0.f, 0.f, 0.f, 0.f, 0.f, 0.f, 0.f, 0.f};
    float den = 0.f;

    for (int i = start; i < end; i++) {
        int s = srcs[i];
        int e = order[i];
        const float4* kp = (const float4*)(k + (size_t)s * DNODE + co);
        float4 k0 = kp[0], k1 = kp[1];

        uint4 eu = *(const uint4*)(eemb + (size_t)e * DNODE + co);
        const __half2* hp = (const __half2*)&eu;
        float2 ea = __half22float2(hp[0]);
        float2 eb = __half22float2(hp[1]);
        float2 ec = __half22float2(hp[2]);
        float2 ed = __half22float2(hp[3]);
        float4 e0 = make_float4(ea.x, ea.y, eb.x, eb.y);
        float4 e1 = make_float4(ec.x, ec.y, ed.x, ed.y);

        float dot = q0.x * (k0.x + e0.x) + q0.y * (k0.y + e0.y)
                  + q0.z * (k0.z + e0.z) + q0.w * (k0.w + e0.w)
                  + q1.x * (k1.x + e1.x) + q1.y * (k1.y + e1.y)
                  + q1.z * (k1.z + e1.z) + q1.w * (k1.w + e1.w);
        dot += __shfl_xor_sync(0xffffffffu, dot, 1);
        dot += __shfl_xor_sync(0xffffffffu, dot, 2);
        dot += __shfl_xor_sync(0xffffffffu, dot, 4);

        float ex = __expf(dot * 0.125f);   // 1/sqrt(64); range-safe in fp32
        den += ex;

        const float4* vp = (const float4*)(v + (size_t)s * DNODE + co);
        float4 v0 = vp[0], v1 = vp[1];
        acc[0] += ex * (v0.x + e0.x); acc[1] += ex * (v0.y + e0.y);
        acc[2] += ex * (v0.z + e0.z); acc[3] += ex * (v0.w + e0.w);
        acc[4] += ex * (v1.x + e1.x); acc[5] += ex * (v1.y + e1.y);
        acc[6] += ex * (v1.z + e1.z); acc[7] += ex * (v1.w + e1.w);
    }

    float inv = 1.0f / (den + 1e-16f);
    const float4* sp = (const float4*)(skip + (size_t)w * DNODE + co);
    float4 s0 = sp[0], s1 = sp[1];
    float r[8];
    r[0] = acc[0] * inv + s0.x; r[1] = acc[1] * inv + s0.y;
    r[2] = acc[2] * inv + s0.z; r[3] = acc[3] * inv + s0.w;
    r[4] = acc[4] * inv + s1.x; r[5] = acc[5] * inv + s1.y;
    r[6] = acc[6] * inv + s1.z; r[7] = acc[7] * inv + s1.w;

    if (mode == 1) {
        __half2 hv[4];
#pragma unroll
        for (int j = 0; j < 4; j++)
            hv[j] = __floats2half2_rn(fmaxf(r[j * 2], 0.f), fmaxf(r[j * 2 + 1], 0.f));
        *(uint4*)(aout + (size_t)w * KPAD + co) = *(const uint4*)hv;
    } else {
        float4* op = (float4*)(outf + (size_t)w * DNODE + co);
        op[0] = make_float4(r[0], r[1], r[2], r[3]);
        op[1] = make_float4(r[4], r[5], r[6], r[7]);
    }
}

// ==================== host side ====================
static void run_layer(const __half* xa, const __half* ea,
                      const __half* wh, const __half* wl, size_t wstride,
                      const float* bias_packed,
                      const int* srcs, const int* order, const int* off,
                      float* q, float* k, float* v, __half* eh, float* skip,
                      float* outf, __half* aout, int mode)
{
    dim3 gn((NN + BM - 1) / BM, 8);
    dim3 ge((EE + BM - 1) / BM, 2);
    gemm_f16<<<gn, NTHR, GEMM_SMEM>>>(xa, wh, wl, bias_packed,
                                      q, k, v, skip, nullptr, NN, KPAD);
    gemm_f16<<<ge, NTHR, GEMM_SMEM>>>(ea, wh + 4 * wstride, wl + 4 * wstride,
                                      nullptr, nullptr, nullptr, nullptr, nullptr,
                                      eh, EE, KEDGE);

    edge_dst<<<(NN * 32 + 255) / 256, 256>>>(q, k, eh, v, srcs, order, off, skip,
                                             outf, aout, mode);
}

extern "C" void kernel_launch(void* const* d_in, const int* in_sizes, int n_in,
                              void* d_out, int out_size)
{
    const float* x   = (const float*)d_in[0];
    const int*   ei  = (const int*)  d_in[1];
    const float* ea_in = (const float*)d_in[2];
    // per layer, weight buffer order: Wq, Wk, Wv, Ws, We
    const float* W1[5] = { (const float*)d_in[3],  (const float*)d_in[5],
                           (const float*)d_in[7],  (const float*)d_in[10],
                           (const float*)d_in[9] };
    const float* W2[5] = { (const float*)d_in[12], (const float*)d_in[14],
                           (const float*)d_in[16], (const float*)d_in[19],
                           (const float*)d_in[18] };
    const int Kin[5] = { DNODE, DNODE, DNODE, DNODE, EDD };

    const int* src = ei;
    const int* dst = ei + EE;
    float* out = (float*)d_out;

    float *q, *k, *v, *skip, *bias;
    __half *eh, *xa, *ea, *wh, *wl;
    int *cnt, *off, *pos, *order, *srcs;
    cudaGetSymbolAddress((void**)&q,     g_q);
    cudaGetSymbolAddress((void**)&k,     g_k);
    cudaGetSymbolAddress((void**)&v,     g_v);
    cudaGetSymbolAddress((void**)&skip,  g_skip);
    cudaGetSymbolAddress((void**)&eh,    g_eh);
    cudaGetSymbolAddress((void**)&cnt,   g_cnt);
    cudaGetSymbolAddress((void**)&off,   g_off);
    cudaGetSymbolAddress((void**)&pos,   g_pos);
    cudaGetSymbolAddress((void**)&order, g_order);
    cudaGetSymbolAddress((void**)&srcs,  g_srcs);
    cudaGetSymbolAddress((void**)&xa,    g_xa);
    cudaGetSymbolAddress((void**)&ea,    g_ea);
    cudaGetSymbolAddress((void**)&wh,    g_wh);
    cudaGetSymbolAddress((void**)&wl,    g_wl);
    cudaGetSymbolAddress((void**)&bias,  g_bias);
    const size_t WS = (size_t)NOUT * KPAD;

    cudaFuncSetAttribute(gemm_f16, cudaFuncAttributeMaxDynamicSharedMemorySize, GEMM_SMEM);

    // ---- edge sort by dst (once; shared by both layers) ----
    zero_cnt<<<(NN + 255) / 256, 256>>>(cnt);
    hist_dst<<<(EE + 255) / 256, 256>>>(dst, cnt);
    scan_cnt<<<1, 1024>>>(cnt, off, pos);
    scatter_edges<<<(EE + 255) / 256, 256>>>(dst, src, pos, order, srcs);

    // ---- conversions ----
    for (int i = 0; i < 5; i++) {
        split_weight_f16<<<(NOUT * KPAD + 255) / 256, 256>>>(W1[i], wh + i * WS,       wl + i * WS,       Kin[i]);
        split_weight_f16<<<(NOUT * KPAD + 255) / 256, 256>>>(W2[i], wh + (5 + i) * WS, wl + (5 + i) * WS, Kin[i]);
    }
    pack_bias<<<4, 256>>>((const float*)d_in[4],  (const float*)d_in[6],
                          (const float*)d_in[8],  (const float*)d_in[11], bias);
    pack_bias<<<4, 256>>>((const float*)d_in[13], (const float*)d_in[15],
                          (const float*)d_in[17], (const float*)d_in[20], bias + 4 * NOUT);

    feat_f16<<<((size_t)EE * KPAD + 255) / 256, 256>>>(ea_in, ea, EE, EDD, KEDGE);
    feat_f16<<<((size_t)NN * KPAD + 255) / 256, 256>>>(x, xa, NN, DNODE, KPAD);

    // ---- layer 1: edge_dst writes relu(out) as fp16 into xa (layer-2 input) ----
    run_layer(xa, ea, wh, wl, WS, bias, srcs, order, off,
              q, k, v, eh, skip, nullptr, xa, 1);

    // ---- layer 2: edge_dst writes d_out ----
    run_layer(xa, ea, wh + 5 * WS, wl + 5 * WS, WS, bias + 4 * NOUT,
              srcs, order, off, q, k, v, eh, skip, out, nullptr, 0);
}

// round 17
// speedup vs baseline: 1.2530x; 1.2530x over previous
#include <cuda_runtime.h>
#include <cuda_bf16.h>
#include <cuda_fp16.h>
#include <cstdint>

#define NN 50000
#define EE 250000
#define HH 4
#define CC 64
#define DNODE 256
#define EDD 194
#define KPAD 256
#define NOUT 256
#define KEDGE 224

// ---------------- scratch (device globals; no runtime allocation) ----------------
__device__ __half g_q   [(size_t)NN * DNODE];   // fp16 q/k/v (edge_dst gathers)
__device__ __half g_k   [(size_t)NN * DNODE];
__device__ __half g_v   [(size_t)NN * DNODE];
__device__ float  g_skip[(size_t)NN * DNODE];   // fp32 skip (accuracy of final add)
__device__ __half g_eh  [(size_t)EE * DNODE];   // edge embeddings, fp16, original order

// edge sort-by-dst (once per call)
__device__ int g_cnt [NN];
__device__ int g_off [NN + 1];
__device__ int g_pos [NN];
__device__ int g_order[EE];
__device__ int g_srcs [EE];

// node path: bf16 hi/lo (3-product). edge path: fp16 single-limb A (slot ehi),
// fp16 hi/lo We in weight slots 4 & 9 (reinterpreted).
__device__ __nv_bfloat16 g_ahi[(size_t)NN * KPAD];
__device__ __nv_bfloat16 g_alo[(size_t)NN * KPAD];
__device__ __nv_bfloat16 g_ehi[(size_t)EE * KPAD];
__device__ __nv_bfloat16 g_whi[10][(size_t)NOUT * KPAD];
__device__ __nv_bfloat16 g_wlo[10][(size_t)NOUT * KPAD];
__device__ float g_bias[2][4 * NOUT];

// ==================== split HMMA GEMM (single-barrier pipeline, R14/R15 core) ====================
// MODE 0: bf16, 3 products (node GEMMs).  MODE 1: fp16, 2 products, single A limb (edge GEMM).
#define BM 128
#define BN 128
#define BK 32
#define NTHR 512
#define NSTAGE 3
#define LDS_A 40
#define TSZ (BM * LDS_A)
#define STAGE_ELEMS (4 * TSZ)
#define GEMM_SMEM (NSTAGE * STAGE_ELEMS * 2)

__device__ __forceinline__ uint32_t smem_u32(const void* p) {
    uint32_t a;
    asm("{ .reg .u64 t; cvta.to.shared.u64 t, %1; cvt.u32.u64 %0, t; }" : "=r"(a) : "l"(p));
    return a;
}
__device__ __forceinline__ void cpa16(uint32_t dst, const void* src, int szbytes) {
    asm volatile("cp.async.ca.shared.global [%0], [%1], 16, %2;"
                 :: "r"(dst), "l"(src), "r"(szbytes));
}
#define CP_COMMIT() asm volatile("cp.async.commit_group;" ::: "memory")
#define CP_WAIT(n)  asm volatile("cp.async.wait_group %0;" :: "n"(n) : "memory")

__device__ __forceinline__ void ldsm4(uint32_t* r, uint32_t a) {
    asm volatile("ldmatrix.sync.aligned.m8n8.x4.shared.b16 {%0,%1,%2,%3}, [%4];"
                 : "=r"(r[0]), "=r"(r[1]), "=r"(r[2]), "=r"(r[3]) : "r"(a));
}
__device__ __forceinline__ void mma_bf16(float* c, const uint32_t* a, const uint32_t* b) {
    asm volatile(
        "mma.sync.aligned.m16n8k16.row.col.f32.bf16.bf16.f32 "
        "{%0,%1,%2,%3}, {%4,%5,%6,%7}, {%8,%9}, {%0,%1,%2,%3};"
        : "+f"(c[0]), "+f"(c[1]), "+f"(c[2]), "+f"(c[3])
        : "r"(a[0]), "r"(a[1]), "r"(a[2]), "r"(a[3]), "r"(b[0]), "r"(b[1]));
}
__device__ __forceinline__ void mma_fp16(float* c, const uint32_t* a, const uint32_t* b) {
    asm volatile(
        "mma.sync.aligned.m16n8k16.row.col.f32.f16.f16.f32 "
        "{%0,%1,%2,%3}, {%4,%5,%6,%7}, {%8,%9}, {%0,%1,%2,%3};"
        : "+f"(c[0]), "+f"(c[1]), "+f"(c[2]), "+f"(c[3])
        : "r"(a[0]), "r"(a[1]), "r"(a[2]), "r"(a[3]), "r"(b[0]), "r"(b[1]));
}

// MODE 0 (node): blockIdx.y 0..7 over [Wq|Wk|Wv|Ws]; q/k/v stored fp16, skip fp32.
// MODE 1 (edge): EH epilogue (fp16).
template <int MODE>
__global__ __launch_bounds__(NTHR) void gemm_split(
    const __nv_bfloat16* __restrict__ Ahi, const __nv_bfloat16* __restrict__ Alo,
    const __nv_bfloat16* __restrict__ Bhi, const __nv_bfloat16* __restrict__ Blo,
    const float* __restrict__ bias,
    __half* __restrict__ Qh, __half* __restrict__ Kh, __half* __restrict__ Vh,
    float* __restrict__ SKIP,
    __half* __restrict__ EH,
    int M, int K)
{
    extern __shared__ __nv_bfloat16 smem[];

    const int tid  = threadIdx.x;
    const int wid  = tid >> 5;
    const int lane = tid & 31;
    const int m0   = blockIdx.x * BM;
    const int nglob0 = blockIdx.y * BN;

    const int wm = (wid & 3) * 32;
    const int wn = (wid >> 2) * 32;
    const int gr  = lane >> 2;
    const int tig = lane & 3;

    const int r0  = tid >> 2;
    const int cg0 = (tid & 3) * 8;
    const int gmA = m0 + r0;
    const int aok = (gmA < M) ? 16 : 0;
    const size_t arow = (size_t)(aok ? gmA : 0) * KPAD;
    const size_t brow = (size_t)(nglob0 + r0) * KPAD;

    const int nk = K / BK;

    float acc[2][4][4];
#pragma unroll
    for (int i = 0; i < 2; i++)
#pragma unroll
        for (int j = 0; j < 4; j++)
#pragma unroll
            for (int r = 0; r < 4; r++) acc[i][j][r] = 0.f;

    uint32_t sbase = smem_u32(smem);

    auto load_stage = [&](int st, int kc) {
        uint32_t b = sbase + (uint32_t)(st * STAGE_ELEMS) * 2;
        uint32_t d = b + (uint32_t)(r0 * LDS_A + cg0) * 2;
        cpa16(d, Ahi + arow + kc + cg0, aok);
        if (MODE == 0) cpa16(d + (uint32_t)TSZ*2, Alo + arow + kc + cg0, aok);
        cpa16(d + (uint32_t)TSZ*4, Bhi + brow + kc + cg0, 16);
        cpa16(d + (uint32_t)TSZ*6, Blo + brow + kc + cg0, 16);
        CP_COMMIT();
    };

    const int aRow = lane & 15;
    const int aCol = (lane >> 4) * 8;
    const uint32_t aOff = (uint32_t)((wm + aRow) * LDS_A + aCol) * 2;
    const int bRow = wn + (lane & 7) + ((lane >> 4) << 3);
    const int bCol = ((lane >> 3) & 1) * 8;
    const uint32_t bOff = (uint32_t)(bRow * LDS_A + bCol) * 2;

    load_stage(0, 0);
    if (nk > 1) load_stage(1, BK);

    for (int ki = 0; ki < nk; ki++) {
        if (ki + 1 < nk) {
            CP_WAIT(1);
        } else {
            CP_WAIT(0);
        }
        __syncthreads();

        uint32_t stb = sbase + (uint32_t)((ki % NSTAGE) * STAGE_ELEMS) * 2;
        uint32_t aHiB = stb, aLoB = stb + TSZ * 2;
        uint32_t bHiB = stb + TSZ * 4, bLoB = stb + TSZ * 6;

#pragma unroll
        for (int ks = 0; ks < BK; ks += 16) {
            uint32_t ah[2][4], al[2][4];
#pragma unroll
            for (int mt = 0; mt < 2; mt++) {
                uint32_t o = aOff + (uint32_t)(mt * 16 * LDS_A + ks) * 2;
                ldsm4(ah[mt], aHiB + o);
                if (MODE == 0) ldsm4(al[mt], aLoB + o);
            }
            uint32_t bhf[8], blf[8];
#pragma unroll
            for (int p = 0; p < 2; p++) {
                uint32_t o = bOff + (uint32_t)(p * 16 * LDS_A + ks) * 2;
                ldsm4(bhf + 4 * p, bHiB + o);
                ldsm4(blf + 4 * p, bLoB + o);
            }
#pragma unroll
            for (int mt = 0; mt < 2; mt++)
#pragma unroll
                for (int nt = 0; nt < 4; nt++) {
                    if (MODE == 0) {
                        mma_bf16(acc[mt][nt], ah[mt], bhf + nt * 2);
                        mma_bf16(acc[mt][nt], ah[mt], blf + nt * 2);
                        mma_bf16(acc[mt][nt], al[mt], bhf + nt * 2);
                    } else {
                        mma_fp16(acc[mt][nt], ah[mt], bhf + nt * 2);
                        mma_fp16(acc[mt][nt], ah[mt], blf + nt * 2);
                    }
                }
        }

        if (ki + 2 < nk) load_stage((ki + 2) % NSTAGE, (ki + 2) * BK);
    }

    // ---- epilogue ----
    if (MODE == 1) {
#pragma unroll
        for (int nt = 0; nt < 4; nt++) {
            int gc = nglob0 + wn + nt * 8 + tig * 2;
#pragma unroll
            for (int mt = 0; mt < 2; mt++) {
                int gm = m0 + wm + mt * 16 + gr;
                if (gm < M) {
                    __half2 h0 = __floats2half2_rn(acc[mt][nt][0], acc[mt][nt][1]);
                    *(__half2*)(EH + (size_t)gm * NOUT + gc) = h0;
                }
                if (gm + 8 < M) {
                    __half2 h1 = __floats2half2_rn(acc[mt][nt][2], acc[mt][nt][3]);
                    *(__half2*)(EH + (size_t)(gm + 8) * NOUT + gc) = h1;
                }
            }
        }
    } else {
        const int ob = blockIdx.y >> 1;
        const int n0l = (blockIdx.y & 1) * BN;
        if (ob == 3) {
            // skip: fp32 + bias
#pragma unroll
            for (int nt = 0; nt < 4; nt++) {
                int lc = wn + nt * 8 + tig * 2;
                float2 b2 = *(const float2*)(bias + nglob0 + lc);
                int gc = n0l + lc;
#pragma unroll
                for (int mt = 0; mt < 2; mt++) {
                    int gm = m0 + wm + mt * 16 + gr;
                    if (gm < M) {
                        float2 v0 = make_float2(acc[mt][nt][0] + b2.x, acc[mt][nt][1] + b2.y);
                        *(float2*)(SKIP + (size_t)gm * NOUT + gc) = v0;
                    }
                    if (gm + 8 < M) {
                        float2 v1 = make_float2(acc[mt][nt][2] + b2.x, acc[mt][nt][3] + b2.y);
                        *(float2*)(SKIP + (size_t)(gm + 8) * NOUT + gc) = v1;
                    }
                }
            }
        } else {
            __half* C = (ob == 0) ? Qh : (ob == 1) ? Kh : Vh;
#pragma unroll
            for (int nt = 0; nt < 4; nt++) {
                int lc = wn + nt * 8 + tig * 2;
                float2 b2 = *(const float2*)(bias + nglob0 + lc);
                int gc = n0l + lc;
#pragma unroll
                for (int mt = 0; mt < 2; mt++) {
                    int gm = m0 + wm + mt * 16 + gr;
                    if (gm < M) {
                        __half2 h0 = __floats2half2_rn(acc[mt][nt][0] + b2.x, acc[mt][nt][1] + b2.y);
                        *(__half2*)(C + (size_t)gm * NOUT + gc) = h0;
                    }
                    if (gm + 8 < M) {
                        __half2 h1 = __floats2half2_rn(acc[mt][nt][2] + b2.x, acc[mt][nt][3] + b2.y);
                        *(__half2*)(C + (size_t)(gm + 8) * NOUT + gc) = h1;
                    }
                }
            }
        }
    }
}

// ==================== conversion kernels ====================
__global__ void split_feat(const float* __restrict__ X,
                           __nv_bfloat16* __restrict__ hi, __nv_bfloat16* __restrict__ lo,
                           int M, int Kin)
{
    int idx = blockIdx.x * blockDim.x + threadIdx.x;
    if (idx >= M * KPAD) return;
    int k = idx & (KPAD - 1);
    float v = 0.f;
    if (k < Kin) v = X[(size_t)(idx >> 8) * Kin + k];
    __nv_bfloat16 h = __float2bfloat16(v);
    hi[idx] = h;
    lo[idx] = __float2bfloat16(v - __bfloat162float(h));
}

// edge features -> single fp16 limb (original order); only k < KEDGE written
__global__ void feat_edge_f16(const float* __restrict__ ea, __half* __restrict__ hi)
{
    int idx = blockIdx.x * blockDim.x + threadIdx.x;
    if (idx >= EE * KPAD) return;
    int k = idx & (KPAD - 1);
    if (k >= KEDGE) return;
    int i = idx >> 8;
    float v = (k < EDD) ? ea[(size_t)i * EDD + k] : 0.f;
    hi[idx] = __float2half(v);
}

__global__ void split_weight(const float* __restrict__ W,
                             __nv_bfloat16* __restrict__ hi, __nv_bfloat16* __restrict__ lo,
                             int Kin)
{
    int idx = blockIdx.x * blockDim.x + threadIdx.x;
    if (idx >= NOUT * KPAD) return;
    int n = idx & 255, k = idx >> 8;
    float v = (k < Kin) ? W[(size_t)k * NOUT + n] : 0.f;
    __nv_bfloat16 h = __float2bfloat16(v);
    hi[(size_t)n * KPAD + k] = h;
    lo[(size_t)n * KPAD + k] = __float2bfloat16(v - __bfloat162float(h));
}

__global__ void split_weight_f16(const float* __restrict__ W,
                                 __half* __restrict__ hi, __half* __restrict__ lo,
                                 int Kin)
{
    int idx = blockIdx.x * blockDim.x + threadIdx.x;
    if (idx >= NOUT * KPAD) return;
    int n = idx & 255, k = idx >> 8;
    float v = (k < Kin) ? W[(size_t)k * NOUT + n] : 0.f;
    __half h = __float2half(v);
    hi[(size_t)n * KPAD + k] = h;
    lo[(size_t)n * KPAD + k] = __float2half(v - __half2float(h));
}

__global__ void pack_bias(const float* __restrict__ bq, const float* __restrict__ bk,
                          const float* __restrict__ bv, const float* __restrict__ bs,
                          float* __restrict__ out)
{
    int i = blockIdx.x * blockDim.x + threadIdx.x;
    if (i >= 4 * NOUT) return;
    const float* src = (i < 256) ? bq : (i < 512) ? bk : (i < 768) ? bv : bs;
    out[i] = src[i & 255];
}

// ==================== edge sort-by-dst (once per call) ====================
__global__ void zero_cnt(int* __restrict__ cnt) {
    int i = blockIdx.x * blockDim.x + threadIdx.x;
    if (i < NN) cnt[i] = 0;
}
__global__ void hist_dst(const int* __restrict__ dst, int* __restrict__ cnt) {
    int i = blockIdx.x * blockDim.x + threadIdx.x;
    if (i < EE) atomicAdd(&cnt[dst[i]], 1);
}
__global__ __launch_bounds__(1024) void scan_cnt(const int* __restrict__ cnt,
                                                 int* __restrict__ off, int* __restrict__ pos)
{
    __shared__ int ssum[1024];
    const int tid = threadIdx.x;
    const int PER = (NN + 1023) / 1024;
    const int base = tid * PER;
    int s = 0;
    for (int j = 0; j < PER; j++) {
        int i = base + j;
        if (i < NN) s += cnt[i];
    }
    ssum[tid] = s;
    __syncthreads();
    for (int d = 1; d < 1024; d <<= 1) {
        int t = (tid >= d) ? ssum[tid - d] : 0;
        __syncthreads();
        ssum[tid] += t;
        __syncthreads();
    }
    int run = (tid > 0) ? ssum[tid - 1] : 0;
    for (int j = 0; j < PER; j++) {
        int i = base + j;
        if (i < NN) {
            off[i] = run;
            pos[i] = run;
            run += cnt[i];
        }
    }
    if (tid == 1023) off[NN] = run;
}
__global__ void scatter_edges(const int* __restrict__ dst, const int* __restrict__ src,
                              int* __restrict__ pos, int* __restrict__ order,
                              int* __restrict__ srcs)
{
    int i = blockIdx.x * blockDim.x + threadIdx.x;
    if (i >= EE) return;
    int p = atomicAdd(&pos[dst[i]], 1);
    order[p] = i;
    srcs[p] = src[i];
}

// ==================== fused per-dst attention (fp16 q/k/v/e gathers) ====================
__device__ __forceinline__ void h8_to_f(const uint4& u, float4& a, float4& b) {
    const __half2* hp = (const __half2*)&u;
    float2 p0 = __half22float2(hp[0]);
    float2 p1 = __half22float2(hp[1]);
    float2 p2 = __half22float2(hp[2]);
    float2 p3 = __half22float2(hp[3]);
    a = make_float4(p0.x, p0.y, p1.x, p1.y);
    b = make_float4(p2.x, p2.y, p3.x, p3.y);
}

__global__ __launch_bounds__(256) void edge_dst(
    const __half* __restrict__ q, const __half* __restrict__ k,
    const __half* __restrict__ eemb, const __half* __restrict__ v,
    const int* __restrict__ srcs, const int* __restrict__ order,
    const int* __restrict__ off, const float* __restrict__ skip,
    float* __restrict__ outf,
    __nv_bfloat16* __restrict__ hi, __nv_bfloat16* __restrict__ lo,
    int mode)
{
    int w = (blockIdx.x * blockDim.x + threadIdx.x) >> 5;
    if (w >= NN) return;
    const int lane = threadIdx.x & 31;
    const int h = lane >> 3;
    const int part = lane & 7;
    const int co = h * CC + part * 8;

    const int start = off[w], end = off[w + 1];

    float4 q0, q1;
    h8_to_f(*(const uint4*)(q + (size_t)w * DNODE + co), q0, q1);

    float acc[8] = {0.f, 0.f, 0.f, 0.f, 0.f, 0.f, 0.f, 0.f};
    float den = 0.f;

    for (int i = start; i < end; i++) {
        int s = srcs[i];
        int e = order[i];
        float4 k0, k1, e0, e1, v0, v1;
        h8_to_f(*(const uint4*)(k    + (size_t)s * DNODE + co), k0, k1);
        h8_to_f(*(const uint4*)(eemb + (size_t)e * DNODE + co), e0, e1);

        float dot = q0.x * (k0.x + e0.x) + q0.y * (k0.y + e0.y)
                  + q0.z * (k0.z + e0.z) + q0.w * (k0.w + e0.w)
                  + q1.x * (k1.x + e1.x) + q1.y * (k1.y + e1.y)
                  + q1.z * (k1.z + e1.z) + q1.w * (k1.w + e1.w);
        dot += __shfl_xor_sync(0xffffffffu, dot, 1);
        dot += __shfl_xor_sync(0xffffffffu, dot, 2);
        dot += __shfl_xor_sync(0xffffffffu, dot, 4);

        float ex = __expf(dot * 0.125f);   // 1/sqrt(64); range-safe in fp32
        den += ex;

        h8_to_f(*(const uint4*)(v + (size_t)s * DNODE + co), v0, v1);
        acc[0] += ex * (v0.x + e0.x); acc[1] += ex * (v0.y + e0.y);
        acc[2] += ex * (v0.z + e0.z); acc[3] += ex * (v0.w + e0.w);
        acc[4] += ex * (v1.x + e1.x); acc[5] += ex * (v1.y + e1.y);
        acc[6] += ex * (v1.z + e1.z); acc[7] += ex * (v1.w + e1.w);
    }

    float inv = 1.0f / (den + 1e-16f);
    const float4* sp = (const float4*)(skip + (size_t)w * DNODE + co);
    float4 s0 = sp[0], s1 = sp[1];
    float r[8];
    r[0] = acc[0] * inv + s0.x; r[1] = acc[1] * inv + s0.y;
    r[2] = acc[2] * inv + s0.z; r[3] = acc[3] * inv + s0.w;
    r[4] = acc[4] * inv + s1.x; r[5] = acc[5] * inv + s1.y;
    r[6] = acc[6] * inv + s1.z; r[7] = acc[7] * inv + s1.w;

    if (mode == 1) {
        ushort4 hv[2], lv[2];
#pragma unroll
        for (int g = 0; g < 2; g++) {
#pragma unroll
            for (int j = 0; j < 4; j++) {
                float x = fmaxf(r[g * 4 + j], 0.f);
                __nv_bfloat16 hb = __float2bfloat16(x);
                __nv_bfloat16 lb = __float2bfloat16(x - __bfloat162float(hb));
                ((unsigned short*)&hv[g])[j] = *(unsigned short*)&hb;
                ((unsigned short*)&lv[g])[j] = *(unsigned short*)&lb;
            }
        }
        size_t base = (size_t)w * KPAD + co;
        *(ushort4*)(hi + base)     = hv[0];
        *(ushort4*)(lo + base)     = lv[0];
        *(ushort4*)(hi + base + 4) = hv[1];
        *(ushort4*)(lo + base + 4) = lv[1];
    } else {
        float4* op = (float4*)(outf + (size_t)w * DNODE + co);
        op[0] = make_float4(r[0], r[1], r[2], r[3]);
        op[1] = make_float4(r[4], r[5], r[6], r[7]);
    }
}

// ==================== host side ====================
static void run_layer(const __nv_bfloat16* ahi, const __nv_bfloat16* alo,
                      const __nv_bfloat16* ehi,
                      const __nv_bfloat16* whi, const __nv_bfloat16* wlo, size_t wstride,
                      const float* bias_packed,
                      const int* srcs, const int* order, const int* off,
                      __half* q, __half* k, __half* v, __half* eh, float* skip,
                      float* outf, __nv_bfloat16* out_hi, __nv_bfloat16* out_lo, int mode)
{
    dim3 gn((NN + BM - 1) / BM, 8);
    dim3 ge((EE + BM - 1) / BM, 2);
    gemm_split<0><<<gn, NTHR, GEMM_SMEM>>>(ahi, alo, whi, wlo, bias_packed,
                                           q, k, v, skip, nullptr, NN, KPAD);
    gemm_split<1><<<ge, NTHR, GEMM_SMEM>>>(ehi, ehi, whi + 4 * wstride, wlo + 4 * wstride,
                                           nullptr, nullptr, nullptr, nullptr, nullptr,
                                           eh, EE, KEDGE);

    edge_dst<<<(NN * 32 + 255) / 256, 256>>>(q, k, eh, v, srcs, order, off, skip,
                                             outf, out_hi, out_lo, mode);
}

extern "C" void kernel_launch(void* const* d_in, const int* in_sizes, int n_in,
                              void* d_out, int out_size)
{
    const float* x   = (const float*)d_in[0];
    const int*   ei  = (const int*)  d_in[1];
    const float* ea  = (const float*)d_in[2];
    // per layer, weight buffer order: Wq, Wk, Wv, Ws, We
    const float* W1[5] = { (const float*)d_in[3],  (const float*)d_in[5],
                           (const float*)d_in[7],  (const float*)d_in[10],
                           (const float*)d_in[9] };
    const float* W2[5] = { (const float*)d_in[12], (const float*)d_in[14],
                           (const float*)d_in[16], (const float*)d_in[19],
                           (const float*)d_in[18] };
    const int Kin[5] = { DNODE, DNODE, DNODE, DNODE, EDD };

    const int* src = ei;
    const int* dst = ei + EE;
    float* out = (float*)d_out;

    float *skip, *bias;
    __half *q, *k, *v, *eh;
    int *cnt, *off, *pos, *order, *srcs;
    __nv_bfloat16 *ahi, *alo, *ehi, *whi, *wlo;
    cudaGetSymbolAddress((void**)&q,     g_q);
    cudaGetSymbolAddress((void**)&k,     g_k);
    cudaGetSymbolAddress((void**)&v,     g_v);
    cudaGetSymbolAddress((void**)&skip,  g_skip);
    cudaGetSymbolAddress((void**)&eh,    g_eh);
    cudaGetSymbolAddress((void**)&cnt,   g_cnt);
    cudaGetSymbolAddress((void**)&off,   g_off);
    cudaGetSymbolAddress((void**)&pos,   g_pos);
    cudaGetSymbolAddress((void**)&order, g_order);
    cudaGetSymbolAddress((void**)&srcs,  g_srcs);
    cudaGetSymbolAddress((void**)&ahi,   g_ahi);
    cudaGetSymbolAddress((void**)&alo,   g_alo);
    cudaGetSymbolAddress((void**)&ehi,   g_ehi);
    cudaGetSymbolAddress((void**)&whi,   g_whi);
    cudaGetSymbolAddress((void**)&wlo,   g_wlo);
    cudaGetSymbolAddress((void**)&bias,  g_bias);
    const size_t WS = (size_t)NOUT * KPAD;

    cudaFuncSetAttribute(gemm_split<0>, cudaFuncAttributeMaxDynamicSharedMemorySize, GEMM_SMEM);
    cudaFuncSetAttribute(gemm_split<1>, cudaFuncAttributeMaxDynamicSharedMemorySize, GEMM_SMEM);

    // ---- edge sort by dst (once; shared by both layers) ----
    zero_cnt<<<(NN + 255) / 256, 256>>>(cnt);
    hist_dst<<<(EE + 255) / 256, 256>>>(dst, cnt);
    scan_cnt<<<1, 1024>>>(cnt, off, pos);
    scatter_edges<<<(EE + 255) / 256, 256>>>(dst, src, pos, order, srcs);

    // ---- conversions ----
    for (int i = 0; i < 4; i++) {   // node weights: bf16 hi/lo
        split_weight<<<(NOUT * KPAD + 255) / 256, 256>>>(W1[i], whi + i * WS,       wlo + i * WS,       Kin[i]);
        split_weight<<<(NOUT * KPAD + 255) / 256, 256>>>(W2[i], whi + (5 + i) * WS, wlo + (5 + i) * WS, Kin[i]);
    }
    // edge weights (slot 4, 9): fp16 hi/lo
    split_weight_f16<<<(NOUT * KPAD + 255) / 256, 256>>>(W1[4], (__half*)(whi + 4 * WS), (__half*)(wlo + 4 * WS), EDD);
    split_weight_f16<<<(NOUT * KPAD + 255) / 256, 256>>>(W2[4], (__half*)(whi + 9 * WS), (__half*)(wlo + 9 * WS), EDD);

    pack_bias<<<4, 256>>>((const float*)d_in[4],  (const float*)d_in[6],
                          (const float*)d_in[8],  (const float*)d_in[11], bias);
    pack_bias<<<4, 256>>>((const float*)d_in[13], (const float*)d_in[15],
                          (const float*)d_in[17], (const float*)d_in[20], bias + 4 * NOUT);

    feat_edge_f16<<<((size_t)EE * KPAD + 255) / 256, 256>>>(ea, (__half*)ehi);
    split_feat<<<((size_t)NN * KPAD + 255) / 256, 256>>>(x, ahi, alo, NN, DNODE);

    // ---- layer 1: edge_dst writes relu+bf16-split of output (layer-2 input) ----
    run_layer(ahi, alo, ehi, whi, wlo, WS, bias, srcs, order, off,
              q, k, v, eh, skip, nullptr, ahi, alo, 1);

    // ---- layer 2: edge_dst writes d_out ----
    run_layer(ahi, alo, ehi, whi + 5 * WS, wlo + 5 * WS, WS, bias + 4 * NOUT,
              srcs, order, off, q, k, v, eh, skip, out, nullptr, nullptr, 0);
}